// round 16
// baseline (speedup 1.0000x reference)
#include <cuda_runtime.h>
#include <cuda_fp16.h>
#include <cstdint>

#define BATCH 32
#define SLEN  1024
#define EDIM  512
#define UDIM  512
#define DDIM  512
#define SGRP  8

// ---------------- scratch ----------------------------------------------------
__device__ float g_dec_proj[BATCH * UDIM];
__device__ float g_spart[BATCH * SLEN * 4];
__device__ float g_scores[BATCH * SLEN];
__device__ __half g_UaT_h[UDIM * EDIM];          // Ua^T fp16  [U][E]
__device__ __half g_enc_h[BATCH * SLEN * EDIM];  // enc fp16
__device__ float g_ctx_part[SGRP][BATCH][EDIM];

// ---------------- helpers ----------------------------------------------------
__device__ __forceinline__ void cp_async16(uint32_t dst, const void* src) {
    asm volatile("cp.async.cg.shared.global [%0], [%1], 16;"
                 :: "r"(dst), "l"(src) : "memory");
}
__device__ __forceinline__ void cp_commit() {
    asm volatile("cp.async.commit_group;" ::: "memory");
}
template <int N>
__device__ __forceinline__ void cp_wait() {
    asm volatile("cp.async.wait_group %0;" :: "n"(N) : "memory");
}
__device__ __forceinline__ void ldsm4(uint32_t& r0, uint32_t& r1, uint32_t& r2,
                                      uint32_t& r3, uint32_t a) {
    asm volatile("ldmatrix.sync.aligned.m8n8.x4.shared.b16 {%0,%1,%2,%3}, [%4];"
                 : "=r"(r0), "=r"(r1), "=r"(r2), "=r"(r3) : "r"(a));
}
__device__ __forceinline__ void mma_f16(float& d0, float& d1, float& d2, float& d3,
                                        uint32_t a0, uint32_t a1, uint32_t a2,
                                        uint32_t a3, uint32_t b0, uint32_t b1) {
    asm volatile(
        "mma.sync.aligned.m16n8k16.row.col.f32.f16.f16.f32 "
        "{%0,%1,%2,%3}, {%4,%5,%6,%7}, {%8,%9}, {%0,%1,%2,%3};"
        : "+f"(d0), "+f"(d1), "+f"(d2), "+f"(d3)
        : "r"(a0), "r"(a1), "r"(a2), "r"(a3), "r"(b0), "r"(b1));
}
__device__ __forceinline__ float fast_tanh(float x) {
    const float e2x = __expf(2.0f * x);
    return 1.0f - __fdividef(2.0f, e2x + 1.0f);
}
__device__ __forceinline__ uint32_t pack_h2(__half lo, __half hi) {
    return (uint32_t)__half_as_ushort(lo) |
           ((uint32_t)__half_as_ushort(hi) << 16);
}

// ---------------- K-1: convert enc -> fp16 (streaming) ----------------------
__global__ __launch_bounds__(256) void conv_enc_kernel(const float* __restrict__ enc) {
    const size_t gid = (size_t)blockIdx.x * 256 + threadIdx.x;   // 8 elems each
    const float4 v0 = *reinterpret_cast<const float4*>(enc + gid * 8);
    const float4 v1 = *reinterpret_cast<const float4*>(enc + gid * 8 + 4);
    uint32_t h[4];
    h[0] = pack_h2(__float2half_rn(v0.x), __float2half_rn(v0.y));
    h[1] = pack_h2(__float2half_rn(v0.z), __float2half_rn(v0.w));
    h[2] = pack_h2(__float2half_rn(v1.x), __float2half_rn(v1.y));
    h[3] = pack_h2(__float2half_rn(v1.z), __float2half_rn(v1.w));
    *reinterpret_cast<uint4*>(g_enc_h + gid * 8) = *reinterpret_cast<uint4*>(h);
}

// ---------------- K0: fused transpose(Ua) + decproj (288 small blocks) ------
__global__ __launch_bounds__(256) void weights_prep_kernel(
    const float* __restrict__ Ua, const float* __restrict__ hid,
    const float* __restrict__ Wa) {
    const int bid = blockIdx.x;
    const int tid = threadIdx.x;
    if (bid < 256) {
        __shared__ float t[32][33];
        const int u0 = (bid & 15) * 32, e0 = (bid >> 4) * 32;
        const int tx = tid & 31, ty = tid >> 5;   // 32 x 8
        #pragma unroll
        for (int i = 0; i < 32; i += 8)
            t[ty + i][tx] = Ua[(size_t)(e0 + ty + i) * UDIM + u0 + tx];
        __syncthreads();
        #pragma unroll
        for (int i = 0; i < 32; i += 8)
            g_UaT_h[(size_t)(u0 + ty + i) * EDIM + e0 + tx] =
                __float2half_rn(t[tx][ty + i]);
    } else {
        __shared__ float h[DDIM];
        const int b = bid - 256;
        h[tid] = hid[b * DDIM + tid];
        h[tid + 256] = hid[b * DDIM + tid + 256];
        __syncthreads();
        #pragma unroll
        for (int j = 0; j < 2; ++j) {
            const int u = tid + j * 256;
            float a0 = 0.f, a1 = 0.f;
            #pragma unroll 8
            for (int k = 0; k < DDIM; k += 2) {
                a0 = fmaf(h[k],     Wa[(size_t)k * UDIM + u],       a0);
                a1 = fmaf(h[k + 1], Wa[(size_t)(k + 1) * UDIM + u], a1);
            }
            g_dec_proj[b * UDIM + u] = a0 + a1;
        }
    }
}

// ---------------- K2: fp16 mma.sync fused scores (R11 config) ---------------
// CTA: 128 s-rows x 128 u-cols, BK=64, 256 threads (8 warps: 2m x 4n),
// warp tile 64x32. 2-stage cp.async, ~77KB SMEM -> 2 CTAs/SM.
#define RS   144                  // 64 fp16 = 128B + 16B pad
#define BK   64
#define KT   (EDIM / BK)          // 8
#define OFF_A  0                  // 128*144 = 18432
#define OFF_B  18432
#define STG    36864              // bytes per stage
#define OFF_DP (2 * STG)          // 73728, 128 floats
#define OFF_VA (OFF_DP + 512)
#define OFF_SP (OFF_VA + 512)     // 128 rows x 4 n-warps
#define SMEM_TOTAL (OFF_SP + 2048)

__global__ __launch_bounds__(256, 2) void scores_kernel(const float* __restrict__ Va) {
    extern __shared__ char smem[];
    const uint32_t sb = (uint32_t)__cvta_generic_to_shared(smem);

    const int tid = threadIdx.x;
    const int wid = tid >> 5, lane = tid & 31;
    const int g = lane >> 2, t = lane & 3;
    const int warp_m = (wid & 1) * 64;
    const int warp_n = (wid >> 1) * 32;
    const int stile = blockIdx.x, utile = blockIdx.y, b = blockIdx.z;

    float* s_dp = (float*)(smem + OFF_DP);
    float* s_va = (float*)(smem + OFF_VA);
    if (tid < 128) {
        s_dp[tid] = g_dec_proj[b * UDIM + utile * 128 + tid];
        s_va[tid] = Va[utile * 128 + tid];
    }

    const __half* Ap = g_enc_h + ((size_t)b * SLEN + (size_t)stile * 128) * EDIM;
    const __half* Bp = g_UaT_h + (size_t)(utile * 128) * EDIM;

    // cp.async mapping: 128 rows x 8 chunks(16B) = 1024 chunks, 4/thread
    int c_r[4], c_s[4];
    #pragma unroll
    for (int i = 0; i < 4; ++i) {
        const int c = tid + i * 256;
        c_r[i] = c >> 3;
        c_s[i] = c & 7;
    }

    auto issue_stage = [&](int kt, int st) {
        const uint32_t so = sb + (uint32_t)st * STG;
        const int ke = kt * BK;
        #pragma unroll
        for (int i = 0; i < 4; ++i) {
            const uint32_t d = c_r[i] * RS + c_s[i] * 16;
            const size_t s = (size_t)c_r[i] * EDIM + ke + c_s[i] * 8;
            cp_async16(so + OFF_A + d, Ap + s);
            cp_async16(so + OFF_B + d, Bp + s);
        }
        cp_commit();
    };

    issue_stage(0, 0);
    issue_stage(1, 1);

    // ldmatrix per-lane offsets (bytes)
    const uint32_t a_off =
        (uint32_t)((warp_m + (lane & 7) + ((lane >> 3) & 1) * 8) * RS +
                   ((lane >> 4) & 1) * 16);
    const uint32_t b_off =
        (uint32_t)((warp_n + (lane & 7) + ((lane >> 4) & 1) * 8) * RS +
                   ((lane >> 3) & 1) * 16);

    float acc[4][4][4];
    #pragma unroll
    for (int mf = 0; mf < 4; ++mf)
        #pragma unroll
        for (int nf = 0; nf < 4; ++nf)
            #pragma unroll
            for (int r = 0; r < 4; ++r) acc[mf][nf][r] = 0.f;

    for (int kt = 0; kt < KT; ++kt) {
        if (kt < KT - 1) cp_wait<1>();
        else             cp_wait<0>();
        __syncthreads();                     // stage kt ready; kt-1 consumed

        const uint32_t stb = sb + (uint32_t)(kt & 1) * STG;
        #pragma unroll
        for (int k16 = 0; k16 < 4; ++k16) {
            const uint32_t kbo = (uint32_t)k16 * 32;
            uint32_t ah[4][4], bb[4][2];
            #pragma unroll
            for (int mf = 0; mf < 4; ++mf)
                ldsm4(ah[mf][0], ah[mf][1], ah[mf][2], ah[mf][3],
                      stb + OFF_A + a_off + (uint32_t)mf * (16 * RS) + kbo);
            ldsm4(bb[0][0], bb[0][1], bb[1][0], bb[1][1],
                  stb + OFF_B + b_off + kbo);
            ldsm4(bb[2][0], bb[2][1], bb[3][0], bb[3][1],
                  stb + OFF_B + b_off + (uint32_t)(16 * RS) + kbo);
            #pragma unroll
            for (int nf = 0; nf < 4; ++nf)
                #pragma unroll
                for (int mf = 0; mf < 4; ++mf)
                    mma_f16(acc[mf][nf][0], acc[mf][nf][1], acc[mf][nf][2],
                            acc[mf][nf][3], ah[mf][0], ah[mf][1], ah[mf][2],
                            ah[mf][3], bb[nf][0], bb[nf][1]);
        }
        __syncthreads();                     // stage fully consumed
        if (kt + 2 < KT) issue_stage(kt + 2, kt & 1);
    }

    // ---- epilogue: tanh(x + dp) * Va, reduce to row sums ----
    float rs[8];
    #pragma unroll
    for (int j = 0; j < 8; ++j) rs[j] = 0.f;
    #pragma unroll
    for (int mf = 0; mf < 4; ++mf)
        #pragma unroll
        for (int nf = 0; nf < 4; ++nf) {
            const int un = warp_n + nf * 8 + 2 * t;
            const float dp0 = s_dp[un], dp1 = s_dp[un + 1];
            const float v0 = s_va[un], v1 = s_va[un + 1];
            rs[mf * 2 + 0] += fast_tanh(acc[mf][nf][0] + dp0) * v0 +
                              fast_tanh(acc[mf][nf][1] + dp1) * v1;
            rs[mf * 2 + 1] += fast_tanh(acc[mf][nf][2] + dp0) * v0 +
                              fast_tanh(acc[mf][nf][3] + dp1) * v1;
        }
    #pragma unroll
    for (int j = 0; j < 8; ++j) {
        rs[j] += __shfl_xor_sync(0xffffffffu, rs[j], 1);
        rs[j] += __shfl_xor_sync(0xffffffffu, rs[j], 2);
    }
    __syncthreads();
    float* s_sp = (float*)(smem + OFF_SP);   // [128 rows][4 n-warps]
    const int nw = wid >> 1;
    if (t == 0) {
        #pragma unroll
        for (int mf = 0; mf < 4; ++mf) {
            s_sp[(warp_m + mf * 16 + g) * 4 + nw]     = rs[mf * 2];
            s_sp[(warp_m + mf * 16 + 8 + g) * 4 + nw] = rs[mf * 2 + 1];
        }
    }
    __syncthreads();
    if (tid < 128) {
        const float s = s_sp[tid * 4] + s_sp[tid * 4 + 1] +
                        s_sp[tid * 4 + 2] + s_sp[tid * 4 + 3];
        g_spart[((size_t)b * SLEN + stile * 128 + tid) * 4 + utile] = s;
    }
}

// ---------------- K3: sum partials + softmax (512 thr) ----------------------
__device__ __forceinline__ float warp_max(float v) {
    #pragma unroll
    for (int o = 16; o; o >>= 1) v = fmaxf(v, __shfl_xor_sync(0xffffffffu, v, o));
    return v;
}
__device__ __forceinline__ float warp_sum(float v) {
    #pragma unroll
    for (int o = 16; o; o >>= 1) v += __shfl_xor_sync(0xffffffffu, v, o);
    return v;
}
__global__ __launch_bounds__(512) void softmax_kernel() {
    const int b = blockIdx.x;
    const int tid = threadIdx.x;          // 512 threads, 2 scores each
    __shared__ float red[16];
    float sc[2];
    #pragma unroll
    for (int j = 0; j < 2; ++j) {
        const float4 p = *reinterpret_cast<const float4*>(
            &g_spart[((size_t)b * SLEN + tid * 2 + j) * 4]);
        sc[j] = (p.x + p.y) + (p.z + p.w);
    }
    float m = fmaxf(sc[0], sc[1]);
    m = warp_max(m);
    if ((tid & 31) == 0) red[tid >> 5] = m;
    __syncthreads();
    m = red[0];
    #pragma unroll
    for (int w = 1; w < 16; ++w) m = fmaxf(m, red[w]);

    float e[2], s;
    e[0] = expf(sc[0] - m); e[1] = expf(sc[1] - m);
    s = e[0] + e[1];
    s = warp_sum(s);
    __syncthreads();
    if ((tid & 31) == 0) red[tid >> 5] = s;
    __syncthreads();
    s = 0.f;
    #pragma unroll
    for (int w = 0; w < 16; ++w) s += red[w];
    const float inv = 1.0f / s;
    float2 o;
    o.x = e[0] * inv; o.y = e[1] * inv;
    *reinterpret_cast<float2*>(&g_scores[b * SLEN + tid * 2]) = o;
}

// ---------------- K4: context partials from fp16 enc  grid(B,8) x 512 -------
__global__ __launch_bounds__(512) void context_kernel() {
    __shared__ float a[128];
    __shared__ float part[4][512];
    const int b = blockIdx.x, sg = blockIdx.y;
    const int tid = threadIdx.x;
    const int s_base = sg * 128;

    if (tid < 128) a[tid] = g_scores[b * SLEN + s_base + tid];
    __syncthreads();

    const int e4 = (tid & 127) * 4;
    const int sr = tid >> 7;                  // 0..3
    const __half* p = g_enc_h + ((size_t)b * SLEN + s_base) * EDIM + e4;
    float4 acc = {0.f, 0.f, 0.f, 0.f};
    #pragma unroll
    for (int it = 0; it < 4; ++it) {          // 8 independent loads per iter
        const int s0 = sr + it * 32;
        uint2 u[8];
        #pragma unroll
        for (int j = 0; j < 8; ++j)
            u[j] = *reinterpret_cast<const uint2*>(p + (size_t)(s0 + j * 4) * EDIM);
        #pragma unroll
        for (int j = 0; j < 8; ++j) {
            const float aw = a[s0 + j * 4];
            const float2 va = __half22float2(*reinterpret_cast<const __half2*>(&u[j].x));
            const float2 vb = __half22float2(*reinterpret_cast<const __half2*>(&u[j].y));
            acc.x = fmaf(aw, va.x, acc.x);
            acc.y = fmaf(aw, va.y, acc.y);
            acc.z = fmaf(aw, vb.x, acc.z);
            acc.w = fmaf(aw, vb.y, acc.w);
        }
    }
    *reinterpret_cast<float4*>(&part[sr][e4]) = acc;
    __syncthreads();
    if (tid < 128) {
        float4 r0 = *reinterpret_cast<float4*>(&part[0][tid * 4]);
        float4 r1 = *reinterpret_cast<float4*>(&part[1][tid * 4]);
        float4 r2 = *reinterpret_cast<float4*>(&part[2][tid * 4]);
        float4 r3 = *reinterpret_cast<float4*>(&part[3][tid * 4]);
        float4 o;
        o.x = r0.x + r1.x + r2.x + r3.x;
        o.y = r0.y + r1.y + r2.y + r3.y;
        o.z = r0.z + r1.z + r2.z + r3.z;
        o.w = r0.w + r1.w + r2.w + r3.w;
        *reinterpret_cast<float4*>(&g_ctx_part[sg][b][tid * 4]) = o;
    }
}

// ---------------- K5: reduce 8 context partials -----------------------------
__global__ void ctx_reduce_kernel(float* __restrict__ out) {
    const int b = blockIdx.x;
    const int tid = threadIdx.x;              // 128 threads, float4
    float4 o = {0.f, 0.f, 0.f, 0.f};
    #pragma unroll
    for (int sg = 0; sg < SGRP; ++sg) {
        const float4 r = *reinterpret_cast<float4*>(&g_ctx_part[sg][b][tid * 4]);
        o.x += r.x; o.y += r.y; o.z += r.z; o.w += r.w;
    }
    *reinterpret_cast<float4*>(&out[b * EDIM + tid * 4]) = o;
}

// ---------------- launch -----------------------------------------------------
extern "C" void kernel_launch(void* const* d_in, const int* in_sizes, int n_in,
                              void* d_out, int out_size) {
    const float* enc = (const float*)d_in[0];   // [B, S, E]
    const float* hid = (const float*)d_in[1];   // [B, D]
    const float* Wa  = (const float*)d_in[2];   // [D, U]
    const float* Ua  = (const float*)d_in[3];   // [E, U]
    const float* Va  = (const float*)d_in[4];   // [U]
    float* out = (float*)d_out;                 // [B, E]

    cudaFuncSetAttribute(scores_kernel,
                         cudaFuncAttributeMaxDynamicSharedMemorySize, SMEM_TOTAL);

    conv_enc_kernel<<<(BATCH * SLEN * EDIM) / (256 * 8), 256>>>(enc);
    weights_prep_kernel<<<256 + BATCH, 256>>>(Ua, hid, Wa);
    dim3 g2(SLEN / 128, UDIM / 128, BATCH);
    scores_kernel<<<g2, 256, SMEM_TOTAL>>>(Va);
    softmax_kernel<<<BATCH, 512>>>();
    dim3 g4(BATCH, SGRP);
    context_kernel<<<g4, 512>>>();
    ctx_reduce_kernel<<<BATCH, 128>>>(out);
}

// round 17
// speedup vs baseline: 1.2628x; 1.2628x over previous
#include <cuda_runtime.h>
#include <cuda_fp16.h>
#include <cstdint>

#define BATCH 32
#define SLEN  1024
#define EDIM  512
#define UDIM  512
#define DDIM  512
#define SGRP  8

// ---------------- scratch ----------------------------------------------------
__device__ float g_dec_proj[BATCH * UDIM];
__device__ float g_spart[BATCH * SLEN * 4];
__device__ float g_scores[BATCH * SLEN];
__device__ __half g_UaT_h[UDIM * EDIM];          // Ua^T fp16  [U][E]
__device__ __half g_enc_h[BATCH * SLEN * EDIM];  // enc fp16
__device__ float g_ctx_part[SGRP][BATCH][EDIM];

// ---------------- helpers ----------------------------------------------------
__device__ __forceinline__ void cp_async16(uint32_t dst, const void* src) {
    asm volatile("cp.async.cg.shared.global [%0], [%1], 16;"
                 :: "r"(dst), "l"(src) : "memory");
}
__device__ __forceinline__ void cp_commit() {
    asm volatile("cp.async.commit_group;" ::: "memory");
}
template <int N>
__device__ __forceinline__ void cp_wait() {
    asm volatile("cp.async.wait_group %0;" :: "n"(N) : "memory");
}
__device__ __forceinline__ void ldsm4(uint32_t& r0, uint32_t& r1, uint32_t& r2,
                                      uint32_t& r3, uint32_t a) {
    asm volatile("ldmatrix.sync.aligned.m8n8.x4.shared.b16 {%0,%1,%2,%3}, [%4];"
                 : "=r"(r0), "=r"(r1), "=r"(r2), "=r"(r3) : "r"(a));
}
__device__ __forceinline__ void mma_f16(float& d0, float& d1, float& d2, float& d3,
                                        uint32_t a0, uint32_t a1, uint32_t a2,
                                        uint32_t a3, uint32_t b0, uint32_t b1) {
    asm volatile(
        "mma.sync.aligned.m16n8k16.row.col.f32.f16.f16.f32 "
        "{%0,%1,%2,%3}, {%4,%5,%6,%7}, {%8,%9}, {%0,%1,%2,%3};"
        : "+f"(d0), "+f"(d1), "+f"(d2), "+f"(d3)
        : "r"(a0), "r"(a1), "r"(a2), "r"(a3), "r"(b0), "r"(b1));
}
__device__ __forceinline__ float fast_tanh(float x) {
    const float e2x = __expf(2.0f * x);
    return 1.0f - __fdividef(2.0f, e2x + 1.0f);
}
__device__ __forceinline__ uint32_t pack_h2(__half lo, __half hi) {
    return (uint32_t)__half_as_ushort(lo) |
           ((uint32_t)__half_as_ushort(hi) << 16);
}

// ---------------- K-1: convert enc -> fp16 (streaming) ----------------------
__global__ __launch_bounds__(256) void conv_enc_kernel(const float* __restrict__ enc) {
    const size_t gid = (size_t)blockIdx.x * 256 + threadIdx.x;   // 8 elems each
    const float4 v0 = *reinterpret_cast<const float4*>(enc + gid * 8);
    const float4 v1 = *reinterpret_cast<const float4*>(enc + gid * 8 + 4);
    uint32_t h[4];
    h[0] = pack_h2(__float2half_rn(v0.x), __float2half_rn(v0.y));
    h[1] = pack_h2(__float2half_rn(v0.z), __float2half_rn(v0.w));
    h[2] = pack_h2(__float2half_rn(v1.x), __float2half_rn(v1.y));
    h[3] = pack_h2(__float2half_rn(v1.z), __float2half_rn(v1.w));
    *reinterpret_cast<uint4*>(g_enc_h + gid * 8) = *reinterpret_cast<uint4*>(h);
}

// ---------------- K0: transpose Ua -> UaT fp16 ------------------------------
__global__ void transpose_kernel(const float* __restrict__ Ua) {
    __shared__ float t[32][33];
    const int u0 = blockIdx.x * 32, e0 = blockIdx.y * 32;
    const int tx = threadIdx.x, ty = threadIdx.y;   // 32 x 8
    #pragma unroll
    for (int i = 0; i < 32; i += 8)
        t[ty + i][tx] = Ua[(size_t)(e0 + ty + i) * UDIM + u0 + tx];
    __syncthreads();
    #pragma unroll
    for (int i = 0; i < 32; i += 8)
        g_UaT_h[(size_t)(u0 + ty + i) * EDIM + e0 + tx] =
            __float2half_rn(t[tx][ty + i]);
}

// ---------------- K1: dec_proj = hidden_dec @ Wa ----------------------------
__global__ void decproj_kernel(const float* __restrict__ hidden,
                               const float* __restrict__ Wa) {
    __shared__ float h[DDIM];
    const int b = blockIdx.x;
    const int tid = threadIdx.x;
    h[tid] = hidden[b * DDIM + tid];
    __syncthreads();
    float a0 = 0.f, a1 = 0.f;
    #pragma unroll 8
    for (int k = 0; k < DDIM; k += 2) {
        a0 = fmaf(h[k],     Wa[(size_t)k * UDIM + tid],       a0);
        a1 = fmaf(h[k + 1], Wa[(size_t)(k + 1) * UDIM + tid], a1);
    }
    g_dec_proj[b * UDIM + tid] = a0 + a1;
}

// ---------------- K2: fp16 mma.sync fused scores (R11 config) ---------------
// CTA: 128 s-rows x 128 u-cols, BK=64, 256 threads (8 warps: 2m x 4n),
// warp tile 64x32. 2-stage cp.async, ~77KB SMEM -> 2 CTAs/SM.
#define RS   144                  // 64 fp16 = 128B + 16B pad
#define BK   64
#define KT   (EDIM / BK)          // 8
#define OFF_A  0                  // 128*144 = 18432
#define OFF_B  18432
#define STG    36864              // bytes per stage
#define OFF_DP (2 * STG)          // 73728, 128 floats
#define OFF_VA (OFF_DP + 512)
#define OFF_SP (OFF_VA + 512)     // 128 rows x 4 n-warps
#define SMEM_TOTAL (OFF_SP + 2048)

__global__ __launch_bounds__(256, 2) void scores_kernel(const float* __restrict__ Va) {
    extern __shared__ char smem[];
    const uint32_t sb = (uint32_t)__cvta_generic_to_shared(smem);

    const int tid = threadIdx.x;
    const int wid = tid >> 5, lane = tid & 31;
    const int g = lane >> 2, t = lane & 3;
    const int warp_m = (wid & 1) * 64;
    const int warp_n = (wid >> 1) * 32;
    const int stile = blockIdx.x, utile = blockIdx.y, b = blockIdx.z;

    float* s_dp = (float*)(smem + OFF_DP);
    float* s_va = (float*)(smem + OFF_VA);
    if (tid < 128) {
        s_dp[tid] = g_dec_proj[b * UDIM + utile * 128 + tid];
        s_va[tid] = Va[utile * 128 + tid];
    }

    const __half* Ap = g_enc_h + ((size_t)b * SLEN + (size_t)stile * 128) * EDIM;
    const __half* Bp = g_UaT_h + (size_t)(utile * 128) * EDIM;

    // cp.async mapping: 128 rows x 8 chunks(16B) = 1024 chunks, 4/thread
    int c_r[4], c_s[4];
    #pragma unroll
    for (int i = 0; i < 4; ++i) {
        const int c = tid + i * 256;
        c_r[i] = c >> 3;
        c_s[i] = c & 7;
    }

    auto issue_stage = [&](int kt, int st) {
        const uint32_t so = sb + (uint32_t)st * STG;
        const int ke = kt * BK;
        #pragma unroll
        for (int i = 0; i < 4; ++i) {
            const uint32_t d = c_r[i] * RS + c_s[i] * 16;
            const size_t s = (size_t)c_r[i] * EDIM + ke + c_s[i] * 8;
            cp_async16(so + OFF_A + d, Ap + s);
            cp_async16(so + OFF_B + d, Bp + s);
        }
        cp_commit();
    };

    issue_stage(0, 0);
    issue_stage(1, 1);

    // ldmatrix per-lane offsets (bytes)
    const uint32_t a_off =
        (uint32_t)((warp_m + (lane & 7) + ((lane >> 3) & 1) * 8) * RS +
                   ((lane >> 4) & 1) * 16);
    const uint32_t b_off =
        (uint32_t)((warp_n + (lane & 7) + ((lane >> 4) & 1) * 8) * RS +
                   ((lane >> 3) & 1) * 16);

    float acc[4][4][4];
    #pragma unroll
    for (int mf = 0; mf < 4; ++mf)
        #pragma unroll
        for (int nf = 0; nf < 4; ++nf)
            #pragma unroll
            for (int r = 0; r < 4; ++r) acc[mf][nf][r] = 0.f;

    for (int kt = 0; kt < KT; ++kt) {
        if (kt < KT - 1) cp_wait<1>();
        else             cp_wait<0>();
        __syncthreads();                     // stage kt ready; kt-1 consumed

        const uint32_t stb = sb + (uint32_t)(kt & 1) * STG;
        #pragma unroll
        for (int k16 = 0; k16 < 4; ++k16) {
            const uint32_t kbo = (uint32_t)k16 * 32;
            uint32_t ah[4][4], bb[4][2];
            #pragma unroll
            for (int mf = 0; mf < 4; ++mf)
                ldsm4(ah[mf][0], ah[mf][1], ah[mf][2], ah[mf][3],
                      stb + OFF_A + a_off + (uint32_t)mf * (16 * RS) + kbo);
            ldsm4(bb[0][0], bb[0][1], bb[1][0], bb[1][1],
                  stb + OFF_B + b_off + kbo);
            ldsm4(bb[2][0], bb[2][1], bb[3][0], bb[3][1],
                  stb + OFF_B + b_off + (uint32_t)(16 * RS) + kbo);
            #pragma unroll
            for (int nf = 0; nf < 4; ++nf)
                #pragma unroll
                for (int mf = 0; mf < 4; ++mf)
                    mma_f16(acc[mf][nf][0], acc[mf][nf][1], acc[mf][nf][2],
                            acc[mf][nf][3], ah[mf][0], ah[mf][1], ah[mf][2],
                            ah[mf][3], bb[nf][0], bb[nf][1]);
        }
        __syncthreads();                     // stage fully consumed
        if (kt + 2 < KT) issue_stage(kt + 2, kt & 1);
    }

    // ---- epilogue: tanh(x + dp) * Va, reduce to row sums ----
    float rs[8];
    #pragma unroll
    for (int j = 0; j < 8; ++j) rs[j] = 0.f;
    #pragma unroll
    for (int mf = 0; mf < 4; ++mf)
        #pragma unroll
        for (int nf = 0; nf < 4; ++nf) {
            const int un = warp_n + nf * 8 + 2 * t;
            const float dp0 = s_dp[un], dp1 = s_dp[un + 1];
            const float v0 = s_va[un], v1 = s_va[un + 1];
            rs[mf * 2 + 0] += fast_tanh(acc[mf][nf][0] + dp0) * v0 +
                              fast_tanh(acc[mf][nf][1] + dp1) * v1;
            rs[mf * 2 + 1] += fast_tanh(acc[mf][nf][2] + dp0) * v0 +
                              fast_tanh(acc[mf][nf][3] + dp1) * v1;
        }
    #pragma unroll
    for (int j = 0; j < 8; ++j) {
        rs[j] += __shfl_xor_sync(0xffffffffu, rs[j], 1);
        rs[j] += __shfl_xor_sync(0xffffffffu, rs[j], 2);
    }
    __syncthreads();
    float* s_sp = (float*)(smem + OFF_SP);   // [128 rows][4 n-warps]
    const int nw = wid >> 1;
    if (t == 0) {
        #pragma unroll
        for (int mf = 0; mf < 4; ++mf) {
            s_sp[(warp_m + mf * 16 + g) * 4 + nw]     = rs[mf * 2];
            s_sp[(warp_m + mf * 16 + 8 + g) * 4 + nw] = rs[mf * 2 + 1];
        }
    }
    __syncthreads();
    if (tid < 128) {
        const float s = s_sp[tid * 4] + s_sp[tid * 4 + 1] +
                        s_sp[tid * 4 + 2] + s_sp[tid * 4 + 3];
        g_spart[((size_t)b * SLEN + stile * 128 + tid) * 4 + utile] = s;
    }
}

// ---------------- K3: sum partials + softmax --------------------------------
__device__ __forceinline__ float warp_max(float v) {
    #pragma unroll
    for (int o = 16; o; o >>= 1) v = fmaxf(v, __shfl_xor_sync(0xffffffffu, v, o));
    return v;
}
__device__ __forceinline__ float warp_sum(float v) {
    #pragma unroll
    for (int o = 16; o; o >>= 1) v += __shfl_xor_sync(0xffffffffu, v, o);
    return v;
}
__global__ void softmax_kernel() {
    const int b = blockIdx.x;
    const int tid = threadIdx.x;          // 256 threads, 4 scores each
    __shared__ float red[8];
    float sc[4];
    #pragma unroll
    for (int j = 0; j < 4; ++j) {
        const float4 p = *reinterpret_cast<const float4*>(
            &g_spart[((size_t)b * SLEN + tid * 4 + j) * 4]);
        sc[j] = (p.x + p.y) + (p.z + p.w);
    }
    float m = fmaxf(fmaxf(sc[0], sc[1]), fmaxf(sc[2], sc[3]));
    m = warp_max(m);
    if ((tid & 31) == 0) red[tid >> 5] = m;
    __syncthreads();
    m = red[0];
    #pragma unroll
    for (int w = 1; w < 8; ++w) m = fmaxf(m, red[w]);

    float e[4], s = 0.f;
    #pragma unroll
    for (int j = 0; j < 4; ++j) { e[j] = expf(sc[j] - m); s += e[j]; }
    s = warp_sum(s);
    __syncthreads();
    if ((tid & 31) == 0) red[tid >> 5] = s;
    __syncthreads();
    s = 0.f;
    #pragma unroll
    for (int w = 0; w < 8; ++w) s += red[w];
    const float inv = 1.0f / s;
    float4 o;
    o.x = e[0] * inv; o.y = e[1] * inv; o.z = e[2] * inv; o.w = e[3] * inv;
    *reinterpret_cast<float4*>(&g_scores[b * SLEN + tid * 4]) = o;
}

// ---------------- K4: context partials from fp16 enc  grid(B,8) x 512 -------
__global__ __launch_bounds__(512) void context_kernel() {
    __shared__ float a[128];
    __shared__ float part[4][512];
    const int b = blockIdx.x, sg = blockIdx.y;
    const int tid = threadIdx.x;
    const int s_base = sg * 128;

    if (tid < 128) a[tid] = g_scores[b * SLEN + s_base + tid];
    __syncthreads();

    const int e4 = (tid & 127) * 4;
    const int sr = tid >> 7;                  // 0..3
    const __half* p = g_enc_h + ((size_t)b * SLEN + s_base) * EDIM + e4;
    float4 acc = {0.f, 0.f, 0.f, 0.f};
    #pragma unroll
    for (int it = 0; it < 4; ++it) {          // 8 independent loads per iter
        const int s0 = sr + it * 32;
        uint2 u[8];
        #pragma unroll
        for (int j = 0; j < 8; ++j)
            u[j] = *reinterpret_cast<const uint2*>(p + (size_t)(s0 + j * 4) * EDIM);
        #pragma unroll
        for (int j = 0; j < 8; ++j) {
            const float aw = a[s0 + j * 4];
            const float2 va = __half22float2(*reinterpret_cast<const __half2*>(&u[j].x));
            const float2 vb = __half22float2(*reinterpret_cast<const __half2*>(&u[j].y));
            acc.x = fmaf(aw, va.x, acc.x);
            acc.y = fmaf(aw, va.y, acc.y);
            acc.z = fmaf(aw, vb.x, acc.z);
            acc.w = fmaf(aw, vb.y, acc.w);
        }
    }
    *reinterpret_cast<float4*>(&part[sr][e4]) = acc;
    __syncthreads();
    if (tid < 128) {
        float4 r0 = *reinterpret_cast<float4*>(&part[0][tid * 4]);
        float4 r1 = *reinterpret_cast<float4*>(&part[1][tid * 4]);
        float4 r2 = *reinterpret_cast<float4*>(&part[2][tid * 4]);
        float4 r3 = *reinterpret_cast<float4*>(&part[3][tid * 4]);
        float4 o;
        o.x = r0.x + r1.x + r2.x + r3.x;
        o.y = r0.y + r1.y + r2.y + r3.y;
        o.z = r0.z + r1.z + r2.z + r3.z;
        o.w = r0.w + r1.w + r2.w + r3.w;
        *reinterpret_cast<float4*>(&g_ctx_part[sg][b][tid * 4]) = o;
    }
}

// ---------------- K5: reduce 8 context partials -----------------------------
__global__ void ctx_reduce_kernel(float* __restrict__ out) {
    const int b = blockIdx.x;
    const int tid = threadIdx.x;              // 128 threads, float4
    float4 o = {0.f, 0.f, 0.f, 0.f};
    #pragma unroll
    for (int sg = 0; sg < SGRP; ++sg) {
        const float4 r = *reinterpret_cast<float4*>(&g_ctx_part[sg][b][tid * 4]);
        o.x += r.x; o.y += r.y; o.z += r.z; o.w += r.w;
    }
    *reinterpret_cast<float4*>(&out[b * EDIM + tid * 4]) = o;
}

// ---------------- launch -----------------------------------------------------
extern "C" void kernel_launch(void* const* d_in, const int* in_sizes, int n_in,
                              void* d_out, int out_size) {
    const float* enc = (const float*)d_in[0];   // [B, S, E]
    const float* hid = (const float*)d_in[1];   // [B, D]
    const float* Wa  = (const float*)d_in[2];   // [D, U]
    const float* Ua  = (const float*)d_in[3];   // [E, U]
    const float* Va  = (const float*)d_in[4];   // [U]
    float* out = (float*)d_out;                 // [B, E]

    cudaFuncSetAttribute(scores_kernel,
                         cudaFuncAttributeMaxDynamicSharedMemorySize, SMEM_TOTAL);

    conv_enc_kernel<<<(BATCH * SLEN * EDIM) / (256 * 8), 256>>>(enc);
    dim3 gt(16, 16);
    transpose_kernel<<<gt, dim3(32, 8)>>>(Ua);
    decproj_kernel<<<BATCH, DDIM>>>(hid, Wa);
    dim3 g2(SLEN / 128, UDIM / 128, BATCH);
    scores_kernel<<<g2, 256, SMEM_TOTAL>>>(Va);
    softmax_kernel<<<BATCH, 256>>>();
    dim3 g4(BATCH, SGRP);
    context_kernel<<<g4, 512>>>();
    ctx_reduce_kernel<<<BATCH, 128>>>(out);
}